// round 2
// baseline (speedup 1.0000x reference)
#include <cuda_runtime.h>
#include <math.h>

#define NB_   7
#define S_    16
#define D_    128
#define B_    32
#define T_    2048
#define KMAX_ 31
#define TT1   32
#define TT2   16
#define TT3   16

__constant__ int c_ks[NB_] = {31, 21, 15, 11, 7, 5, 3};

// Scratch (device globals; no allocations allowed)
__device__ float g_h[(size_t)NB_ * B_ * T_ * D_];        // post-LN1 h  [nb][b][t][d]
__device__ float g_p[(size_t)B_ * T_ * NB_ * 4 * S_];    // cat layout  [b][t][nb][4S]

__device__ __forceinline__ float gelu_exact(float v) {
    return 0.5f * v * (1.0f + erff(v * 0.70710678118654752440f));
}

// ---------------------------------------------------------------------------
// Kernel 1: per-band 1D conv (masked taps only) + bias + LayerNorm -> g_h
// grid (T/TT1, B, NB), block 128 (one thread per d)
// ---------------------------------------------------------------------------
__global__ __launch_bounds__(128) void k_conv_ln(
    const float* __restrict__ x, const float* __restrict__ conv_w,
    const float* __restrict__ conv_b, const float* __restrict__ dec_g,
    const float* __restrict__ dec_b)
{
    __shared__ float xs[(TT1 + KMAX_ - 1) * S_];   // 62*16 floats
    __shared__ float hs[TT1 * D_];                 // 32*128 floats

    const int band = blockIdx.z, b = blockIdx.y;
    const int t0 = blockIdx.x * TT1;
    const int tid = threadIdx.x;

    // load x window [t0-15, t0+TT1+14] x 16 channels, zero-padded
    const float* xb = x + (size_t)b * T_ * S_;
    for (int i = tid; i < (TT1 + KMAX_ - 1) * S_; i += 128) {
        int row = i >> 4, s = i & 15;
        int gt = t0 + row - (KMAX_ / 2);
        xs[i] = (gt >= 0 && gt < T_) ? xb[gt * S_ + s] : 0.0f;
    }
    __syncthreads();

    float acc[TT1];
#pragma unroll
    for (int tt = 0; tt < TT1; ++tt) acc[tt] = 0.0f;

    const int Kb = c_ks[band];
    const int off = (KMAX_ - Kb) >> 1;
    const float* wb = conv_w + ((size_t)band * KMAX_ * S_) * D_ + tid;

    for (int k = off; k < off + Kb; ++k) {
#pragma unroll
        for (int sg = 0; sg < S_; sg += 4) {
            float w0 = wb[(k * S_ + sg + 0) * D_];
            float w1 = wb[(k * S_ + sg + 1) * D_];
            float w2 = wb[(k * S_ + sg + 2) * D_];
            float w3 = wb[(k * S_ + sg + 3) * D_];
#pragma unroll
            for (int tt = 0; tt < TT1; ++tt) {
                float4 xv = *(const float4*)&xs[(tt + k) * S_ + sg];
                acc[tt] = fmaf(xv.x, w0, acc[tt]);
                acc[tt] = fmaf(xv.y, w1, acc[tt]);
                acc[tt] = fmaf(xv.z, w2, acc[tt]);
                acc[tt] = fmaf(xv.w, w3, acc[tt]);
            }
        }
    }

    const float cb = conv_b[band * D_ + tid];
#pragma unroll
    for (int tt = 0; tt < TT1; ++tt) hs[tt * D_ + tid] = acc[tt] + cb;
    __syncthreads();

    // LayerNorm over D=128 per token; warp handles 8 tokens
    const int lane = tid & 31, warp = tid >> 5;
    float gv[4], bv[4];
#pragma unroll
    for (int c = 0; c < 4; ++c) {
        gv[c] = dec_g[band * D_ + lane + 32 * c];
        bv[c] = dec_b[band * D_ + lane + 32 * c];
    }
    float* hb = g_h + (((size_t)band * B_ + b) * T_ + t0) * D_;
    for (int i = 0; i < 8; ++i) {
        int tt = warp * 8 + i;
        float v[4]; float s = 0.0f;
#pragma unroll
        for (int c = 0; c < 4; ++c) { v[c] = hs[tt * D_ + lane + 32 * c]; s += v[c]; }
#pragma unroll
        for (int o = 16; o; o >>= 1) s += __shfl_xor_sync(0xffffffffu, s, o);
        float mean = s * (1.0f / 128.0f);
        float q = 0.0f;
#pragma unroll
        for (int c = 0; c < 4; ++c) { float d0 = v[c] - mean; q = fmaf(d0, d0, q); }
#pragma unroll
        for (int o = 16; o; o >>= 1) q += __shfl_xor_sync(0xffffffffu, q, o);
        float rstd = rsqrtf(q * (1.0f / 128.0f) + 1e-5f);
#pragma unroll
        for (int c = 0; c < 4; ++c)
            hb[(size_t)tt * D_ + lane + 32 * c] = (v[c] - mean) * rstd * gv[c] + bv[c];
    }
}

// ---------------------------------------------------------------------------
// Kernel 2: per-band  LN2 -> FFN (gelu) -> residual -> proj  -> g_p
// grid (T/TT2, B, NB), block 256
// ---------------------------------------------------------------------------
__global__ __launch_bounds__(256) void k_ffn(
    const float* __restrict__ n2_g, const float* __restrict__ n2_b,
    const float* __restrict__ w1, const float* __restrict__ b1,
    const float* __restrict__ w2, const float* __restrict__ b2,
    const float* __restrict__ pw, const float* __restrict__ pb)
{
    __shared__ float hs[TT2 * 128];
    __shared__ float zs[TT2 * 128];   // z, later reused as band_out
    __shared__ float us[TT2 * 256];

    const int band = blockIdx.z, b = blockIdx.y;
    const int t0 = blockIdx.x * TT2;
    const int tid = threadIdx.x;

    const float* hb = g_h + (((size_t)band * B_ + b) * T_ + t0) * 128;
    for (int i = tid; i < TT2 * 128; i += 256) hs[i] = hb[i];
    __syncthreads();

    // LN2: 8 warps x 2 tokens
    {
        const int lane = tid & 31, warp = tid >> 5;
        float gv[4], bv[4];
#pragma unroll
        for (int c = 0; c < 4; ++c) {
            gv[c] = n2_g[band * 128 + lane + 32 * c];
            bv[c] = n2_b[band * 128 + lane + 32 * c];
        }
        for (int i = 0; i < 2; ++i) {
            int tt = warp * 2 + i;
            float v[4]; float s = 0.0f;
#pragma unroll
            for (int c = 0; c < 4; ++c) { v[c] = hs[tt * 128 + lane + 32 * c]; s += v[c]; }
#pragma unroll
            for (int o = 16; o; o >>= 1) s += __shfl_xor_sync(0xffffffffu, s, o);
            float mean = s * (1.0f / 128.0f);
            float q = 0.0f;
#pragma unroll
            for (int c = 0; c < 4; ++c) { float d0 = v[c] - mean; q = fmaf(d0, d0, q); }
#pragma unroll
            for (int o = 16; o; o >>= 1) q += __shfl_xor_sync(0xffffffffu, q, o);
            float rstd = rsqrtf(q * (1.0f / 128.0f) + 1e-5f);
#pragma unroll
            for (int c = 0; c < 4; ++c)
                zs[tt * 128 + lane + 32 * c] = (v[c] - mean) * rstd * gv[c] + bv[c];
        }
    }
    __syncthreads();

    // GEMM1: u = gelu(z @ W1 + b1), thread = output col e (0..255)
    {
        const int e = tid;
        float acc[TT2];
#pragma unroll
        for (int tt = 0; tt < TT2; ++tt) acc[tt] = 0.0f;
        const float* wc = w1 + (size_t)band * 128 * 256 + e;
        for (int d = 0; d < 128; d += 4) {
            float w0 = wc[(d + 0) * 256];
            float wv1 = wc[(d + 1) * 256];
            float wv2 = wc[(d + 2) * 256];
            float wv3 = wc[(d + 3) * 256];
#pragma unroll
            for (int tt = 0; tt < TT2; ++tt) {
                float4 zv = *(const float4*)&zs[tt * 128 + d];
                acc[tt] = fmaf(zv.x, w0, acc[tt]);
                acc[tt] = fmaf(zv.y, wv1, acc[tt]);
                acc[tt] = fmaf(zv.z, wv2, acc[tt]);
                acc[tt] = fmaf(zv.w, wv3, acc[tt]);
            }
        }
        const float bb = b1[band * 256 + e];
#pragma unroll
        for (int tt = 0; tt < TT2; ++tt) us[tt * 256 + e] = gelu_exact(acc[tt] + bb);
    }
    __syncthreads();

    // GEMM2: band_out = h + u @ W2 + b2 ; thread = (d, token half)
    {
        const int d = tid & 127, tg = tid >> 7;
        float acc[8];
#pragma unroll
        for (int j = 0; j < 8; ++j) acc[j] = 0.0f;
        const float* wc = w2 + (size_t)band * 256 * 128 + d;
        for (int e = 0; e < 256; e += 4) {
            float w0 = wc[(e + 0) * 128];
            float wv1 = wc[(e + 1) * 128];
            float wv2 = wc[(e + 2) * 128];
            float wv3 = wc[(e + 3) * 128];
#pragma unroll
            for (int j = 0; j < 8; ++j) {
                int tt = tg * 8 + j;
                float4 uv = *(const float4*)&us[tt * 256 + e];
                acc[j] = fmaf(uv.x, w0, acc[j]);
                acc[j] = fmaf(uv.y, wv1, acc[j]);
                acc[j] = fmaf(uv.z, wv2, acc[j]);
                acc[j] = fmaf(uv.w, wv3, acc[j]);
            }
        }
        const float bb = b2[band * 128 + d];
#pragma unroll
        for (int j = 0; j < 8; ++j) {
            int tt = tg * 8 + j;
            zs[tt * 128 + d] = hs[tt * 128 + d] + acc[j] + bb;   // zs := band_out
        }
    }
    __syncthreads();

    // proj: p = band_out @ proj_w + proj_b ; thread = (j, token quarter)
    {
        const int jc = tid & 63, tq = tid >> 6;
        float acc[4];
#pragma unroll
        for (int j = 0; j < 4; ++j) acc[j] = 0.0f;
        const float* wc = pw + (size_t)band * 128 * 64 + jc;
        for (int d = 0; d < 128; d += 4) {
            float w0 = wc[(d + 0) * 64];
            float wv1 = wc[(d + 1) * 64];
            float wv2 = wc[(d + 2) * 64];
            float wv3 = wc[(d + 3) * 64];
#pragma unroll
            for (int j = 0; j < 4; ++j) {
                int tt = tq * 4 + j;
                float4 bv4 = *(const float4*)&zs[tt * 128 + d];
                acc[j] = fmaf(bv4.x, w0, acc[j]);
                acc[j] = fmaf(bv4.y, wv1, acc[j]);
                acc[j] = fmaf(bv4.z, wv2, acc[j]);
                acc[j] = fmaf(bv4.w, wv3, acc[j]);
            }
        }
        const float bb = pb[band * 64 + jc];
#pragma unroll
        for (int j = 0; j < 4; ++j) {
            int tt = tq * 4 + j;
            g_p[(((size_t)b * T_ + t0 + tt) * NB_ + band) * 64 + jc] = acc[j] + bb;
        }
    }
}

// ---------------------------------------------------------------------------
// Kernel 3: mix MLP over cat [B*T, 448] -> gelu -> [.,128] -> [.,16]
// grid (B*T/TT3), block 256
// ---------------------------------------------------------------------------
__global__ __launch_bounds__(256) void k_mix(
    const float* __restrict__ w1, const float* __restrict__ b1,
    const float* __restrict__ w2, const float* __restrict__ b2,
    float* __restrict__ out)
{
    __shared__ float cs[TT3 * 448];
    __shared__ float ms[TT3 * 128];

    const int bt0 = blockIdx.x * TT3;
    const int tid = threadIdx.x;

    const float* cb = g_p + (size_t)bt0 * 448;
    for (int i = tid; i < TT3 * 448; i += 256) cs[i] = cb[i];
    __syncthreads();

    // GEMM1 448->128 + gelu; thread = (e, token half)
    {
        const int e = tid & 127, tg = tid >> 7;
        float acc[8];
#pragma unroll
        for (int j = 0; j < 8; ++j) acc[j] = 0.0f;
        const float* wc = w1 + e;
        for (int i = 0; i < 448; i += 4) {
            float w0 = wc[(i + 0) * 128];
            float wv1 = wc[(i + 1) * 128];
            float wv2 = wc[(i + 2) * 128];
            float wv3 = wc[(i + 3) * 128];
#pragma unroll
            for (int j = 0; j < 8; ++j) {
                int tt = tg * 8 + j;
                float4 cv = *(const float4*)&cs[tt * 448 + i];
                acc[j] = fmaf(cv.x, w0, acc[j]);
                acc[j] = fmaf(cv.y, wv1, acc[j]);
                acc[j] = fmaf(cv.z, wv2, acc[j]);
                acc[j] = fmaf(cv.w, wv3, acc[j]);
            }
        }
        const float bb = b1[e];
#pragma unroll
        for (int j = 0; j < 8; ++j)
            ms[(tg * 8 + j) * 128 + e] = gelu_exact(acc[j] + bb);
    }
    __syncthreads();

    // GEMM2 128->16; one thread per (token, out-col)
    {
        const int o = tid & 15, tt = tid >> 4;
        float acc = 0.0f;
        const float* wc = w2 + o;
        for (int e = 0; e < 128; e += 4) {
            float4 mv = *(const float4*)&ms[tt * 128 + e];
            acc = fmaf(mv.x, wc[(e + 0) * 16], acc);
            acc = fmaf(mv.y, wc[(e + 1) * 16], acc);
            acc = fmaf(mv.z, wc[(e + 2) * 16], acc);
            acc = fmaf(mv.w, wc[(e + 3) * 16], acc);
        }
        out[(size_t)(bt0 + tt) * 16 + o] = acc + b2[o];
    }
}

// ---------------------------------------------------------------------------
extern "C" void kernel_launch(void* const* d_in, const int* in_sizes, int n_in,
                              void* d_out, int out_size)
{
    const float* x      = (const float*)d_in[0];
    const float* conv_w = (const float*)d_in[1];
    const float* conv_b = (const float*)d_in[2];
    const float* dec_g  = (const float*)d_in[3];
    const float* dec_b  = (const float*)d_in[4];
    const float* n2_g   = (const float*)d_in[5];
    const float* n2_b   = (const float*)d_in[6];
    const float* ffn_w1 = (const float*)d_in[7];
    const float* ffn_b1 = (const float*)d_in[8];
    const float* ffn_w2 = (const float*)d_in[9];
    const float* ffn_b2 = (const float*)d_in[10];
    const float* proj_w = (const float*)d_in[11];
    const float* proj_b = (const float*)d_in[12];
    const float* mix_w1 = (const float*)d_in[13];
    const float* mix_b1 = (const float*)d_in[14];
    const float* mix_w2 = (const float*)d_in[15];
    const float* mix_b2 = (const float*)d_in[16];
    float* out = (float*)d_out;

    dim3 g1(T_ / TT1, B_, NB_);
    k_conv_ln<<<g1, 128>>>(x, conv_w, conv_b, dec_g, dec_b);

    dim3 g2(T_ / TT2, B_, NB_);
    k_ffn<<<g2, 256>>>(n2_g, n2_b, ffn_w1, ffn_b1, ffn_w2, ffn_b2, proj_w, proj_b);

    dim3 g3((B_ * T_) / TT3);
    k_mix<<<g3, 256>>>(mix_w1, mix_b1, mix_w2, mix_b2, out);
}

// round 3
// speedup vs baseline: 1.8582x; 1.8582x over previous
#include <cuda_runtime.h>
#include <math.h>
#include <stdint.h>

#define NB_   7
#define S_    16
#define D_    128
#define B_    32
#define T_    2048
#define KMAX_ 31
#define TT1   32

__constant__ int c_ks[NB_] = {31, 21, 15, 11, 7, 5, 3};

// Scratch (device globals; no allocations allowed)
__device__ float g_h[(size_t)NB_ * B_ * T_ * D_];        // post-LN1 h  [nb][b][t][d]
__device__ float g_p[(size_t)B_ * T_ * NB_ * 4 * S_];    // cat layout  [b][t][nb][4S]

__device__ __forceinline__ float gelu_exact(float v) {
    return 0.5f * v * (1.0f + erff(v * 0.70710678118654752440f));
}

__device__ __forceinline__ uint32_t f2tf(float f) {
    uint32_t r;
    asm("cvt.rna.tf32.f32 %0, %1;" : "=r"(r) : "f"(f));
    return r;
}

__device__ __forceinline__ void mma_tf32(float c[4],
    uint32_t a0, uint32_t a1, uint32_t a2, uint32_t a3,
    uint32_t b0, uint32_t b1)
{
    asm volatile(
        "mma.sync.aligned.m16n8k8.row.col.f32.tf32.tf32.f32 "
        "{%0,%1,%2,%3},{%4,%5,%6,%7},{%8,%9},{%0,%1,%2,%3};"
        : "+f"(c[0]), "+f"(c[1]), "+f"(c[2]), "+f"(c[3])
        : "r"(a0), "r"(a1), "r"(a2), "r"(a3), "r"(b0), "r"(b1));
}

// ---------------------------------------------------------------------------
// Kernel 1: per-band 1D conv (masked taps only) + bias + LayerNorm -> g_h
// grid (T/TT1, B, NB), block 128 (one thread per d)  [unchanged]
// ---------------------------------------------------------------------------
__global__ __launch_bounds__(128) void k_conv_ln(
    const float* __restrict__ x, const float* __restrict__ conv_w,
    const float* __restrict__ conv_b, const float* __restrict__ dec_g,
    const float* __restrict__ dec_b)
{
    __shared__ float xs[(TT1 + KMAX_ - 1) * S_];
    __shared__ float hs[TT1 * D_];

    const int band = blockIdx.z, b = blockIdx.y;
    const int t0 = blockIdx.x * TT1;
    const int tid = threadIdx.x;

    const float* xb = x + (size_t)b * T_ * S_;
    for (int i = tid; i < (TT1 + KMAX_ - 1) * S_; i += 128) {
        int row = i >> 4, s = i & 15;
        int gt = t0 + row - (KMAX_ / 2);
        xs[i] = (gt >= 0 && gt < T_) ? xb[gt * S_ + s] : 0.0f;
    }
    __syncthreads();

    float acc[TT1];
#pragma unroll
    for (int tt = 0; tt < TT1; ++tt) acc[tt] = 0.0f;

    const int Kb = c_ks[band];
    const int off = (KMAX_ - Kb) >> 1;
    const float* wb = conv_w + ((size_t)band * KMAX_ * S_) * D_ + tid;

    for (int k = off; k < off + Kb; ++k) {
#pragma unroll
        for (int sg = 0; sg < S_; sg += 4) {
            float w0 = wb[(k * S_ + sg + 0) * D_];
            float w1 = wb[(k * S_ + sg + 1) * D_];
            float w2 = wb[(k * S_ + sg + 2) * D_];
            float w3 = wb[(k * S_ + sg + 3) * D_];
#pragma unroll
            for (int tt = 0; tt < TT1; ++tt) {
                float4 xv = *(const float4*)&xs[(tt + k) * S_ + sg];
                acc[tt] = fmaf(xv.x, w0, acc[tt]);
                acc[tt] = fmaf(xv.y, w1, acc[tt]);
                acc[tt] = fmaf(xv.z, w2, acc[tt]);
                acc[tt] = fmaf(xv.w, w3, acc[tt]);
            }
        }
    }

    const float cb = conv_b[band * D_ + tid];
#pragma unroll
    for (int tt = 0; tt < TT1; ++tt) hs[tt * D_ + tid] = acc[tt] + cb;
    __syncthreads();

    const int lane = tid & 31, warp = tid >> 5;
    float gv[4], bv[4];
#pragma unroll
    for (int c = 0; c < 4; ++c) {
        gv[c] = dec_g[band * D_ + lane + 32 * c];
        bv[c] = dec_b[band * D_ + lane + 32 * c];
    }
    float* hb = g_h + (((size_t)band * B_ + b) * T_ + t0) * D_;
    for (int i = 0; i < 8; ++i) {
        int tt = warp * 8 + i;
        float v[4]; float s = 0.0f;
#pragma unroll
        for (int c = 0; c < 4; ++c) { v[c] = hs[tt * D_ + lane + 32 * c]; s += v[c]; }
#pragma unroll
        for (int o = 16; o; o >>= 1) s += __shfl_xor_sync(0xffffffffu, s, o);
        float mean = s * (1.0f / 128.0f);
        float q = 0.0f;
#pragma unroll
        for (int c = 0; c < 4; ++c) { float d0 = v[c] - mean; q = fmaf(d0, d0, q); }
#pragma unroll
        for (int o = 16; o; o >>= 1) q += __shfl_xor_sync(0xffffffffu, q, o);
        float rstd = rsqrtf(q * (1.0f / 128.0f) + 1e-5f);
#pragma unroll
        for (int c = 0; c < 4; ++c)
            hb[(size_t)tt * D_ + lane + 32 * c] = (v[c] - mean) * rstd * gv[c] + bv[c];
    }
}

// ---------------------------------------------------------------------------
// Kernel 2 (tensor-core): LN2 -> GEMM1(gelu) -> GEMM2(+h) -> proj -> g_p
// grid (T/32, B, NB), block 256 (8 warps), tf32 mma.sync m16n8k8
// smem: hs[32*132] zs[32*132] us[32*260]  (pads keep frag LDS conflict-free)
// ---------------------------------------------------------------------------
#define ZP 132
#define UP 260

__global__ __launch_bounds__(256) void k_ffn_tc(
    const float* __restrict__ n2_g, const float* __restrict__ n2_b,
    const float* __restrict__ w1, const float* __restrict__ fb1,
    const float* __restrict__ w2, const float* __restrict__ fb2,
    const float* __restrict__ pw, const float* __restrict__ pb)
{
    extern __shared__ float sm[];
    float* hs = sm;                 // 32*132
    float* zs = sm + 32 * ZP;       // 32*132
    float* us = zs + 32 * ZP;       // 32*260

    const int band = blockIdx.z, b = blockIdx.y;
    const int t0 = blockIdx.x * 32;
    const int tid = threadIdx.x;
    const int warp = tid >> 5, lane = tid & 31;
    const int grp = lane >> 2, tig = lane & 3;

    // load h tile [32,128]
    const float* hbp = g_h + (((size_t)band * B_ + b) * T_ + t0) * 128;
    for (int i = tid; i < 32 * 128; i += 256) {
        int r = i >> 7, c = i & 127;
        hs[r * ZP + c] = hbp[i];
    }
    __syncthreads();

    // LN2: warp handles 4 tokens -> zs (tf32-rounded)
    {
        float gv[4], bv[4];
#pragma unroll
        for (int c = 0; c < 4; ++c) {
            gv[c] = n2_g[band * 128 + lane + 32 * c];
            bv[c] = n2_b[band * 128 + lane + 32 * c];
        }
        for (int i = 0; i < 4; ++i) {
            int tt = warp * 4 + i;
            float v[4]; float s = 0.0f;
#pragma unroll
            for (int c = 0; c < 4; ++c) { v[c] = hs[tt * ZP + lane + 32 * c]; s += v[c]; }
#pragma unroll
            for (int o = 16; o; o >>= 1) s += __shfl_xor_sync(0xffffffffu, s, o);
            float mean = s * (1.0f / 128.0f);
            float q = 0.0f;
#pragma unroll
            for (int c = 0; c < 4; ++c) { float d0 = v[c] - mean; q = fmaf(d0, d0, q); }
#pragma unroll
            for (int o = 16; o; o >>= 1) q += __shfl_xor_sync(0xffffffffu, q, o);
            float rstd = rsqrtf(q * (1.0f / 128.0f) + 1e-5f);
#pragma unroll
            for (int c = 0; c < 4; ++c) {
                float zv = (v[c] - mean) * rstd * gv[c] + bv[c];
                zs[tt * ZP + lane + 32 * c] = __uint_as_float(f2tf(zv));
            }
        }
    }
    __syncthreads();

    // GEMM1: u = gelu(z[32,128] @ W1[128,256] + b1). warp n-slice 32 wide.
    {
        float acc[2][4][4];
#pragma unroll
        for (int mt = 0; mt < 2; ++mt)
#pragma unroll
            for (int nt = 0; nt < 4; ++nt)
#pragma unroll
                for (int c = 0; c < 4; ++c) acc[mt][nt][c] = 0.0f;

        const float* w1g = w1 + (size_t)band * 128 * 256;
        for (int k0 = 0; k0 < 128; k0 += 8) {
            uint32_t a[2][4];
#pragma unroll
            for (int mt = 0; mt < 2; ++mt) {
                int r0 = mt * 16 + grp;
                a[mt][0] = __float_as_uint(zs[r0 * ZP + k0 + tig]);
                a[mt][1] = __float_as_uint(zs[(r0 + 8) * ZP + k0 + tig]);
                a[mt][2] = __float_as_uint(zs[r0 * ZP + k0 + tig + 4]);
                a[mt][3] = __float_as_uint(zs[(r0 + 8) * ZP + k0 + tig + 4]);
            }
#pragma unroll
            for (int nt = 0; nt < 4; ++nt) {
                int col = warp * 32 + nt * 8 + grp;
                uint32_t bf0 = f2tf(w1g[(k0 + tig) * 256 + col]);
                uint32_t bf1 = f2tf(w1g[(k0 + tig + 4) * 256 + col]);
#pragma unroll
                for (int mt = 0; mt < 2; ++mt)
                    mma_tf32(acc[mt][nt], a[mt][0], a[mt][1], a[mt][2], a[mt][3], bf0, bf1);
            }
        }
        // epilogue: bias + gelu -> us (tf32-rounded)
#pragma unroll
        for (int nt = 0; nt < 4; ++nt) {
            int col0 = warp * 32 + nt * 8 + tig * 2;
            float bb0 = fb1[band * 256 + col0];
            float bb1 = fb1[band * 256 + col0 + 1];
#pragma unroll
            for (int mt = 0; mt < 2; ++mt) {
                int r0 = mt * 16 + grp;
                us[r0 * UP + col0]           = __uint_as_float(f2tf(gelu_exact(acc[mt][nt][0] + bb0)));
                us[r0 * UP + col0 + 1]       = __uint_as_float(f2tf(gelu_exact(acc[mt][nt][1] + bb1)));
                us[(r0 + 8) * UP + col0]     = __uint_as_float(f2tf(gelu_exact(acc[mt][nt][2] + bb0)));
                us[(r0 + 8) * UP + col0 + 1] = __uint_as_float(f2tf(gelu_exact(acc[mt][nt][3] + bb1)));
            }
        }
    }
    __syncthreads();

    // GEMM2: band_out = h + u[32,256] @ W2[256,128] + b2. warp n-slice 16.
    {
        float acc[2][2][4];
#pragma unroll
        for (int mt = 0; mt < 2; ++mt)
#pragma unroll
            for (int nt = 0; nt < 2; ++nt)
#pragma unroll
                for (int c = 0; c < 4; ++c) acc[mt][nt][c] = 0.0f;

        const float* w2g = w2 + (size_t)band * 256 * 128;
        for (int k0 = 0; k0 < 256; k0 += 8) {
            uint32_t a[2][4];
#pragma unroll
            for (int mt = 0; mt < 2; ++mt) {
                int r0 = mt * 16 + grp;
                a[mt][0] = __float_as_uint(us[r0 * UP + k0 + tig]);
                a[mt][1] = __float_as_uint(us[(r0 + 8) * UP + k0 + tig]);
                a[mt][2] = __float_as_uint(us[r0 * UP + k0 + tig + 4]);
                a[mt][3] = __float_as_uint(us[(r0 + 8) * UP + k0 + tig + 4]);
            }
#pragma unroll
            for (int nt = 0; nt < 2; ++nt) {
                int col = warp * 16 + nt * 8 + grp;
                uint32_t bf0 = f2tf(w2g[(k0 + tig) * 128 + col]);
                uint32_t bf1 = f2tf(w2g[(k0 + tig + 4) * 128 + col]);
#pragma unroll
                for (int mt = 0; mt < 2; ++mt)
                    mma_tf32(acc[mt][nt], a[mt][0], a[mt][1], a[mt][2], a[mt][3], bf0, bf1);
            }
        }
        // epilogue: + h + bias -> zs (band_out, tf32-rounded)
#pragma unroll
        for (int nt = 0; nt < 2; ++nt) {
            int col0 = warp * 16 + nt * 8 + tig * 2;
            float bb0 = fb2[band * 128 + col0];
            float bb1 = fb2[band * 128 + col0 + 1];
#pragma unroll
            for (int mt = 0; mt < 2; ++mt) {
                int r0 = mt * 16 + grp;
                zs[r0 * ZP + col0]           = __uint_as_float(f2tf(acc[mt][nt][0] + bb0 + hs[r0 * ZP + col0]));
                zs[r0 * ZP + col0 + 1]       = __uint_as_float(f2tf(acc[mt][nt][1] + bb1 + hs[r0 * ZP + col0 + 1]));
                zs[(r0 + 8) * ZP + col0]     = __uint_as_float(f2tf(acc[mt][nt][2] + bb0 + hs[(r0 + 8) * ZP + col0]));
                zs[(r0 + 8) * ZP + col0 + 1] = __uint_as_float(f2tf(acc[mt][nt][3] + bb1 + hs[(r0 + 8) * ZP + col0 + 1]));
            }
        }
    }
    __syncthreads();

    // proj: p = band_out[32,128] @ pw[128,64] + pb -> g_p. warp n-slice 8.
    {
        float acc[2][4];
#pragma unroll
        for (int mt = 0; mt < 2; ++mt)
#pragma unroll
            for (int c = 0; c < 4; ++c) acc[mt][c] = 0.0f;

        const float* pwg = pw + (size_t)band * 128 * 64;
        for (int k0 = 0; k0 < 128; k0 += 8) {
            uint32_t a[2][4];
#pragma unroll
            for (int mt = 0; mt < 2; ++mt) {
                int r0 = mt * 16 + grp;
                a[mt][0] = __float_as_uint(zs[r0 * ZP + k0 + tig]);
                a[mt][1] = __float_as_uint(zs[(r0 + 8) * ZP + k0 + tig]);
                a[mt][2] = __float_as_uint(zs[r0 * ZP + k0 + tig + 4]);
                a[mt][3] = __float_as_uint(zs[(r0 + 8) * ZP + k0 + tig + 4]);
            }
            int col = warp * 8 + grp;
            uint32_t bf0 = f2tf(pwg[(k0 + tig) * 64 + col]);
            uint32_t bf1 = f2tf(pwg[(k0 + tig + 4) * 64 + col]);
#pragma unroll
            for (int mt = 0; mt < 2; ++mt)
                mma_tf32(acc[mt], a[mt][0], a[mt][1], a[mt][2], a[mt][3], bf0, bf1);
        }
        int col0 = warp * 8 + tig * 2;
        float bb0 = pb[band * 64 + col0];
        float bb1 = pb[band * 64 + col0 + 1];
#pragma unroll
        for (int mt = 0; mt < 2; ++mt) {
            int r0 = mt * 16 + grp;
            float2 v0 = make_float2(acc[mt][0] + bb0, acc[mt][1] + bb1);
            float2 v1 = make_float2(acc[mt][2] + bb0, acc[mt][3] + bb1);
            *(float2*)&g_p[(((size_t)b * T_ + t0 + r0) * NB_ + band) * 64 + col0] = v0;
            *(float2*)&g_p[(((size_t)b * T_ + t0 + r0 + 8) * NB_ + band) * 64 + col0] = v1;
        }
    }
}

// ---------------------------------------------------------------------------
// Kernel 3 (tensor-core GEMM1): cat[32,448] @ mix_w1[448,128] -> gelu -> ms
// then fp32 FFMA 128->16. grid (B*T/32), block 256.
// smem: cs[32*452] ms[32*132]
// ---------------------------------------------------------------------------
#define CP 452
#define MP 132

__global__ __launch_bounds__(256) void k_mix_tc(
    const float* __restrict__ mw1, const float* __restrict__ mb1,
    const float* __restrict__ mw2, const float* __restrict__ mb2,
    float* __restrict__ out)
{
    extern __shared__ float sm[];
    float* cs = sm;                 // 32*452
    float* ms = sm + 32 * CP;       // 32*132

    const int bt0 = blockIdx.x * 32;
    const int tid = threadIdx.x;
    const int warp = tid >> 5, lane = tid & 31;
    const int grp = lane >> 2, tig = lane & 3;

    const float* cb = g_p + (size_t)bt0 * 448;
    for (int i = tid; i < 32 * 448; i += 256) {
        int r = i / 448, c = i - r * 448;
        cs[r * CP + c] = __uint_as_float(f2tf(cb[i]));
    }
    __syncthreads();

    // GEMM1: [32,448]x[448,128]; warp n-slice 16.
    {
        float acc[2][2][4];
#pragma unroll
        for (int mt = 0; mt < 2; ++mt)
#pragma unroll
            for (int nt = 0; nt < 2; ++nt)
#pragma unroll
                for (int c = 0; c < 4; ++c) acc[mt][nt][c] = 0.0f;

        for (int k0 = 0; k0 < 448; k0 += 8) {
            uint32_t a[2][4];
#pragma unroll
            for (int mt = 0; mt < 2; ++mt) {
                int r0 = mt * 16 + grp;
                a[mt][0] = __float_as_uint(cs[r0 * CP + k0 + tig]);
                a[mt][1] = __float_as_uint(cs[(r0 + 8) * CP + k0 + tig]);
                a[mt][2] = __float_as_uint(cs[r0 * CP + k0 + tig + 4]);
                a[mt][3] = __float_as_uint(cs[(r0 + 8) * CP + k0 + tig + 4]);
            }
#pragma unroll
            for (int nt = 0; nt < 2; ++nt) {
                int col = warp * 16 + nt * 8 + grp;
                uint32_t bf0 = f2tf(mw1[(k0 + tig) * 128 + col]);
                uint32_t bf1 = f2tf(mw1[(k0 + tig + 4) * 128 + col]);
#pragma unroll
                for (int mt = 0; mt < 2; ++mt)
                    mma_tf32(acc[mt][nt], a[mt][0], a[mt][1], a[mt][2], a[mt][3], bf0, bf1);
            }
        }
#pragma unroll
        for (int nt = 0; nt < 2; ++nt) {
            int col0 = warp * 16 + nt * 8 + tig * 2;
            float bb0 = mb1[col0];
            float bb1 = mb1[col0 + 1];
#pragma unroll
            for (int mt = 0; mt < 2; ++mt) {
                int r0 = mt * 16 + grp;
                ms[r0 * MP + col0]           = gelu_exact(acc[mt][nt][0] + bb0);
                ms[r0 * MP + col0 + 1]       = gelu_exact(acc[mt][nt][1] + bb1);
                ms[(r0 + 8) * MP + col0]     = gelu_exact(acc[mt][nt][2] + bb0);
                ms[(r0 + 8) * MP + col0 + 1] = gelu_exact(acc[mt][nt][3] + bb1);
            }
        }
    }
    __syncthreads();

    // GEMM2 128->16 fp32 FFMA; thread=(o, token), two token halves
    {
        const int o = tid & 15, tb = tid >> 4;
        const float* wc = mw2 + o;
        const float bo = mb2[o];
#pragma unroll
        for (int h = 0; h < 2; ++h) {
            int tt = tb + h * 16;
            float acc = 0.0f;
            for (int e = 0; e < 128; e += 4) {
                float4 mv = *(const float4*)&ms[tt * MP + e];
                acc = fmaf(mv.x, wc[(e + 0) * 16], acc);
                acc = fmaf(mv.y, wc[(e + 1) * 16], acc);
                acc = fmaf(mv.z, wc[(e + 2) * 16], acc);
                acc = fmaf(mv.w, wc[(e + 3) * 16], acc);
            }
            out[(size_t)(bt0 + tt) * 16 + o] = acc + bo;
        }
    }
}

// ---------------------------------------------------------------------------
extern "C" void kernel_launch(void* const* d_in, const int* in_sizes, int n_in,
                              void* d_out, int out_size)
{
    const float* x      = (const float*)d_in[0];
    const float* conv_w = (const float*)d_in[1];
    const float* conv_b = (const float*)d_in[2];
    const float* dec_g  = (const float*)d_in[3];
    const float* dec_b  = (const float*)d_in[4];
    const float* n2_g   = (const float*)d_in[5];
    const float* n2_b   = (const float*)d_in[6];
    const float* ffn_w1 = (const float*)d_in[7];
    const float* ffn_b1 = (const float*)d_in[8];
    const float* ffn_w2 = (const float*)d_in[9];
    const float* ffn_b2 = (const float*)d_in[10];
    const float* proj_w = (const float*)d_in[11];
    const float* proj_b = (const float*)d_in[12];
    const float* mix_w1 = (const float*)d_in[13];
    const float* mix_b1 = (const float*)d_in[14];
    const float* mix_w2 = (const float*)d_in[15];
    const float* mix_b2 = (const float*)d_in[16];
    float* out = (float*)d_out;

    const int smem_ffn = (32 * ZP * 2 + 32 * UP) * 4;       // 67072 B
    const int smem_mix = (32 * CP + 32 * MP) * 4;           // 74752 B
    cudaFuncSetAttribute(k_ffn_tc, cudaFuncAttributeMaxDynamicSharedMemorySize, smem_ffn);
    cudaFuncSetAttribute(k_mix_tc, cudaFuncAttributeMaxDynamicSharedMemorySize, smem_mix);

    dim3 g1(T_ / TT1, B_, NB_);
    k_conv_ln<<<g1, 128>>>(x, conv_w, conv_b, dec_g, dec_b);

    dim3 g2(T_ / 32, B_, NB_);
    k_ffn_tc<<<g2, 256, smem_ffn>>>(n2_g, n2_b, ffn_w1, ffn_b1, ffn_w2, ffn_b2, proj_w, proj_b);

    dim3 g3((B_ * T_) / 32);
    k_mix_tc<<<g3, 256, smem_mix>>>(mix_w1, mix_b1, mix_w2, mix_b2, out);
}

// round 4
// speedup vs baseline: 2.1882x; 1.1776x over previous
#include <cuda_runtime.h>
#include <math.h>
#include <stdint.h>

#define NB_   7
#define S_    16
#define D_    128
#define B_    32
#define T_    2048
#define KMAX_ 31

__constant__ int c_ks[NB_] = {31, 21, 15, 11, 7, 5, 3};

// Scratch (device globals; no allocations allowed)
__device__ float g_h[(size_t)NB_ * B_ * T_ * D_];        // post-LN1 h  [nb][b][t][d]
__device__ float g_p[(size_t)B_ * T_ * NB_ * 4 * S_];    // cat layout  [b][t][nb][4S]

__device__ __forceinline__ float gelu_exact(float v) {
    return 0.5f * v * (1.0f + erff(v * 0.70710678118654752440f));
}

__device__ __forceinline__ uint32_t f2tf(float f) {
    uint32_t r;
    asm("cvt.rna.tf32.f32 %0, %1;" : "=r"(r) : "f"(f));
    return r;
}

__device__ __forceinline__ void mma_tf32(float c[4],
    uint32_t a0, uint32_t a1, uint32_t a2, uint32_t a3,
    uint32_t b0, uint32_t b1)
{
    asm volatile(
        "mma.sync.aligned.m16n8k8.row.col.f32.tf32.tf32.f32 "
        "{%0,%1,%2,%3},{%4,%5,%6,%7},{%8,%9},{%0,%1,%2,%3};"
        : "+f"(c[0]), "+f"(c[1]), "+f"(c[2]), "+f"(c[3])
        : "r"(a0), "r"(a1), "r"(a2), "r"(a3), "r"(b0), "r"(b1));
}

// ---------------------------------------------------------------------------
// Kernel 1 (tensor-core): implicit-GEMM conv (masked taps) + bias + LN -> g_h
// grid (T/32, B, NB), block 256 (8 warps). out[32,128] per block.
// A = shifted x patches (smem, row stride 20 => conflict-free frag LDS)
// B = conv_w tap slices straight from GMEM (sector-perfect, L2-resident)
// ---------------------------------------------------------------------------
#define XSTR 20
#define HP   132

__global__ __launch_bounds__(256) void k_conv_tc(
    const float* __restrict__ x, const float* __restrict__ conv_w,
    const float* __restrict__ conv_b, const float* __restrict__ dec_g,
    const float* __restrict__ dec_b)
{
    __shared__ float xs[(32 + KMAX_ - 1) * XSTR];   // 62 rows x stride 20
    __shared__ float hs[32 * HP];

    const int band = blockIdx.z, b = blockIdx.y;
    const int t0 = blockIdx.x * 32;
    const int tid = threadIdx.x;
    const int warp = tid >> 5, lane = tid & 31;
    const int grp = lane >> 2, tig = lane & 3;

    // stage x window rows [t0-15, t0+46], tf32-rounded
    const float* xb = x + (size_t)b * T_ * S_;
    for (int i = tid; i < 62 * S_; i += 256) {
        int row = i >> 4, s = i & 15;
        int gt = t0 + row - (KMAX_ / 2);
        float v = (gt >= 0 && gt < T_) ? xb[gt * S_ + s] : 0.0f;
        xs[row * XSTR + s] = __uint_as_float(f2tf(v));
    }
    __syncthreads();

    // conv as mma: warp owns 16 output cols; 2 m-tiles of 16 tokens
    float acc[2][2][4];
#pragma unroll
    for (int mt = 0; mt < 2; ++mt)
#pragma unroll
        for (int nt = 0; nt < 2; ++nt)
#pragma unroll
            for (int c = 0; c < 4; ++c) acc[mt][nt][c] = 0.0f;

    const int Kb = c_ks[band];
    const int off = (KMAX_ - Kb) >> 1;
    const float* wb = conv_w + (size_t)band * KMAX_ * S_ * D_;

    for (int k = off; k < off + Kb; ++k) {
#pragma unroll
        for (int c8 = 0; c8 < 2; ++c8) {
            const int s0 = c8 * 8;
            uint32_t a[2][4];
#pragma unroll
            for (int mt = 0; mt < 2; ++mt) {
                int r0 = mt * 16 + grp + k;     // shifted row = token + tap
                a[mt][0] = __float_as_uint(xs[r0 * XSTR + s0 + tig]);
                a[mt][1] = __float_as_uint(xs[(r0 + 8) * XSTR + s0 + tig]);
                a[mt][2] = __float_as_uint(xs[r0 * XSTR + s0 + tig + 4]);
                a[mt][3] = __float_as_uint(xs[(r0 + 8) * XSTR + s0 + tig + 4]);
            }
#pragma unroll
            for (int nt = 0; nt < 2; ++nt) {
                int col = warp * 16 + nt * 8 + grp;
                uint32_t bf0 = f2tf(wb[(size_t)(k * S_ + s0 + tig) * D_ + col]);
                uint32_t bf1 = f2tf(wb[(size_t)(k * S_ + s0 + tig + 4) * D_ + col]);
#pragma unroll
                for (int mt = 0; mt < 2; ++mt)
                    mma_tf32(acc[mt][nt], a[mt][0], a[mt][1], a[mt][2], a[mt][3], bf0, bf1);
            }
        }
    }

    // bias -> hs
#pragma unroll
    for (int nt = 0; nt < 2; ++nt) {
        int col0 = warp * 16 + nt * 8 + tig * 2;
        float bb0 = conv_b[band * D_ + col0];
        float bb1 = conv_b[band * D_ + col0 + 1];
#pragma unroll
        for (int mt = 0; mt < 2; ++mt) {
            int r0 = mt * 16 + grp;
            hs[r0 * HP + col0]           = acc[mt][nt][0] + bb0;
            hs[r0 * HP + col0 + 1]       = acc[mt][nt][1] + bb1;
            hs[(r0 + 8) * HP + col0]     = acc[mt][nt][2] + bb0;
            hs[(r0 + 8) * HP + col0 + 1] = acc[mt][nt][3] + bb1;
        }
    }
    __syncthreads();

    // LayerNorm (8 warps x 4 tokens) -> g_h
    {
        float gv[4], bv[4];
#pragma unroll
        for (int c = 0; c < 4; ++c) {
            gv[c] = dec_g[band * D_ + lane + 32 * c];
            bv[c] = dec_b[band * D_ + lane + 32 * c];
        }
        float* hb = g_h + (((size_t)band * B_ + b) * T_ + t0) * D_;
        for (int i = 0; i < 4; ++i) {
            int tt = warp * 4 + i;
            float v[4]; float s = 0.0f;
#pragma unroll
            for (int c = 0; c < 4; ++c) { v[c] = hs[tt * HP + lane + 32 * c]; s += v[c]; }
#pragma unroll
            for (int o = 16; o; o >>= 1) s += __shfl_xor_sync(0xffffffffu, s, o);
            float mean = s * (1.0f / 128.0f);
            float q = 0.0f;
#pragma unroll
            for (int c = 0; c < 4; ++c) { float d0 = v[c] - mean; q = fmaf(d0, d0, q); }
#pragma unroll
            for (int o = 16; o; o >>= 1) q += __shfl_xor_sync(0xffffffffu, q, o);
            float rstd = rsqrtf(q * (1.0f / 128.0f) + 1e-5f);
#pragma unroll
            for (int c = 0; c < 4; ++c)
                hb[(size_t)tt * D_ + lane + 32 * c] = (v[c] - mean) * rstd * gv[c] + bv[c];
        }
    }
}

// ---------------------------------------------------------------------------
// Kernel 2 (tensor-core, 64-token tile): LN2 -> GEMM1(gelu) -> GEMM2(+h) -> proj
// grid (T/64, B, NB), block 256 (8 warps), tf32 mma m16n8k8
// smem (dynamic): hs[64*132] zs[64*132] us[64*260] = 134144 B
// ---------------------------------------------------------------------------
#define ZP 132
#define UP 260
#define MT 4          // 64 tokens = 4 m-tiles

__global__ __launch_bounds__(256) void k_ffn_tc(
    const float* __restrict__ n2_g, const float* __restrict__ n2_b,
    const float* __restrict__ w1, const float* __restrict__ fb1,
    const float* __restrict__ w2, const float* __restrict__ fb2,
    const float* __restrict__ pw, const float* __restrict__ pb)
{
    extern __shared__ float sm[];
    float* hs = sm;                 // 64*132
    float* zs = sm + 64 * ZP;       // 64*132
    float* us = zs + 64 * ZP;       // 64*260

    const int band = blockIdx.z, b = blockIdx.y;
    const int t0 = blockIdx.x * 64;
    const int tid = threadIdx.x;
    const int warp = tid >> 5, lane = tid & 31;
    const int grp = lane >> 2, tig = lane & 3;

    const float* hbp = g_h + (((size_t)band * B_ + b) * T_ + t0) * 128;
    for (int i = tid; i < 64 * 128; i += 256) {
        int r = i >> 7, c = i & 127;
        hs[r * ZP + c] = hbp[i];
    }
    __syncthreads();

    // LN2: warp handles 8 tokens -> zs (tf32-rounded)
    {
        float gv[4], bv[4];
#pragma unroll
        for (int c = 0; c < 4; ++c) {
            gv[c] = n2_g[band * 128 + lane + 32 * c];
            bv[c] = n2_b[band * 128 + lane + 32 * c];
        }
        for (int i = 0; i < 8; ++i) {
            int tt = warp * 8 + i;
            float v[4]; float s = 0.0f;
#pragma unroll
            for (int c = 0; c < 4; ++c) { v[c] = hs[tt * ZP + lane + 32 * c]; s += v[c]; }
#pragma unroll
            for (int o = 16; o; o >>= 1) s += __shfl_xor_sync(0xffffffffu, s, o);
            float mean = s * (1.0f / 128.0f);
            float q = 0.0f;
#pragma unroll
            for (int c = 0; c < 4; ++c) { float d0 = v[c] - mean; q = fmaf(d0, d0, q); }
#pragma unroll
            for (int o = 16; o; o >>= 1) q += __shfl_xor_sync(0xffffffffu, q, o);
            float rstd = rsqrtf(q * (1.0f / 128.0f) + 1e-5f);
#pragma unroll
            for (int c = 0; c < 4; ++c) {
                float zv = (v[c] - mean) * rstd * gv[c] + bv[c];
                zs[tt * ZP + lane + 32 * c] = __uint_as_float(f2tf(zv));
            }
        }
    }
    __syncthreads();

    // GEMM1: u = gelu(z[64,128] @ W1[128,256] + b1). warp n-slice 32 wide.
    {
        float acc[MT][4][4];
#pragma unroll
        for (int mt = 0; mt < MT; ++mt)
#pragma unroll
            for (int nt = 0; nt < 4; ++nt)
#pragma unroll
                for (int c = 0; c < 4; ++c) acc[mt][nt][c] = 0.0f;

        const float* w1g = w1 + (size_t)band * 128 * 256;
        for (int k0 = 0; k0 < 128; k0 += 8) {
            uint32_t a[MT][4];
#pragma unroll
            for (int mt = 0; mt < MT; ++mt) {
                int r0 = mt * 16 + grp;
                a[mt][0] = __float_as_uint(zs[r0 * ZP + k0 + tig]);
                a[mt][1] = __float_as_uint(zs[(r0 + 8) * ZP + k0 + tig]);
                a[mt][2] = __float_as_uint(zs[r0 * ZP + k0 + tig + 4]);
                a[mt][3] = __float_as_uint(zs[(r0 + 8) * ZP + k0 + tig + 4]);
            }
#pragma unroll
            for (int nt = 0; nt < 4; ++nt) {
                int col = warp * 32 + nt * 8 + grp;
                uint32_t bf0 = f2tf(w1g[(k0 + tig) * 256 + col]);
                uint32_t bf1 = f2tf(w1g[(k0 + tig + 4) * 256 + col]);
#pragma unroll
                for (int mt = 0; mt < MT; ++mt)
                    mma_tf32(acc[mt][nt], a[mt][0], a[mt][1], a[mt][2], a[mt][3], bf0, bf1);
            }
        }
#pragma unroll
        for (int nt = 0; nt < 4; ++nt) {
            int col0 = warp * 32 + nt * 8 + tig * 2;
            float bb0 = fb1[band * 256 + col0];
            float bb1 = fb1[band * 256 + col0 + 1];
#pragma unroll
            for (int mt = 0; mt < MT; ++mt) {
                int r0 = mt * 16 + grp;
                us[r0 * UP + col0]           = __uint_as_float(f2tf(gelu_exact(acc[mt][nt][0] + bb0)));
                us[r0 * UP + col0 + 1]       = __uint_as_float(f2tf(gelu_exact(acc[mt][nt][1] + bb1)));
                us[(r0 + 8) * UP + col0]     = __uint_as_float(f2tf(gelu_exact(acc[mt][nt][2] + bb0)));
                us[(r0 + 8) * UP + col0 + 1] = __uint_as_float(f2tf(gelu_exact(acc[mt][nt][3] + bb1)));
            }
        }
    }
    __syncthreads();

    // GEMM2: band_out = h + u[64,256] @ W2[256,128] + b2. warp n-slice 16.
    {
        float acc[MT][2][4];
#pragma unroll
        for (int mt = 0; mt < MT; ++mt)
#pragma unroll
            for (int nt = 0; nt < 2; ++nt)
#pragma unroll
                for (int c = 0; c < 4; ++c) acc[mt][nt][c] = 0.0f;

        const float* w2g = w2 + (size_t)band * 256 * 128;
        for (int k0 = 0; k0 < 256; k0 += 8) {
            uint32_t a[MT][4];
#pragma unroll
            for (int mt = 0; mt < MT; ++mt) {
                int r0 = mt * 16 + grp;
                a[mt][0] = __float_as_uint(us[r0 * UP + k0 + tig]);
                a[mt][1] = __float_as_uint(us[(r0 + 8) * UP + k0 + tig]);
                a[mt][2] = __float_as_uint(us[r0 * UP + k0 + tig + 4]);
                a[mt][3] = __float_as_uint(us[(r0 + 8) * UP + k0 + tig + 4]);
            }
#pragma unroll
            for (int nt = 0; nt < 2; ++nt) {
                int col = warp * 16 + nt * 8 + grp;
                uint32_t bf0 = f2tf(w2g[(k0 + tig) * 128 + col]);
                uint32_t bf1 = f2tf(w2g[(k0 + tig + 4) * 128 + col]);
#pragma unroll
                for (int mt = 0; mt < MT; ++mt)
                    mma_tf32(acc[mt][nt], a[mt][0], a[mt][1], a[mt][2], a[mt][3], bf0, bf1);
            }
        }
#pragma unroll
        for (int nt = 0; nt < 2; ++nt) {
            int col0 = warp * 16 + nt * 8 + tig * 2;
            float bb0 = fb2[band * 128 + col0];
            float bb1 = fb2[band * 128 + col0 + 1];
#pragma unroll
            for (int mt = 0; mt < MT; ++mt) {
                int r0 = mt * 16 + grp;
                zs[r0 * ZP + col0]           = __uint_as_float(f2tf(acc[mt][nt][0] + bb0 + hs[r0 * ZP + col0]));
                zs[r0 * ZP + col0 + 1]       = __uint_as_float(f2tf(acc[mt][nt][1] + bb1 + hs[r0 * ZP + col0 + 1]));
                zs[(r0 + 8) * ZP + col0]     = __uint_as_float(f2tf(acc[mt][nt][2] + bb0 + hs[(r0 + 8) * ZP + col0]));
                zs[(r0 + 8) * ZP + col0 + 1] = __uint_as_float(f2tf(acc[mt][nt][3] + bb1 + hs[(r0 + 8) * ZP + col0 + 1]));
            }
        }
    }
    __syncthreads();

    // proj: p = band_out[64,128] @ pw[128,64] + pb -> g_p. warp n-slice 8.
    {
        float acc[MT][4];
#pragma unroll
        for (int mt = 0; mt < MT; ++mt)
#pragma unroll
            for (int c = 0; c < 4; ++c) acc[mt][c] = 0.0f;

        const float* pwg = pw + (size_t)band * 128 * 64;
        for (int k0 = 0; k0 < 128; k0 += 8) {
            uint32_t a[MT][4];
#pragma unroll
            for (int mt = 0; mt < MT; ++mt) {
                int r0 = mt * 16 + grp;
                a[mt][0] = __float_as_uint(zs[r0 * ZP + k0 + tig]);
                a[mt][1] = __float_as_uint(zs[(r0 + 8) * ZP + k0 + tig]);
                a[mt][2] = __float_as_uint(zs[r0 * ZP + k0 + tig + 4]);
                a[mt][3] = __float_as_uint(zs[(r0 + 8) * ZP + k0 + tig + 4]);
            }
            int col = warp * 8 + grp;
            uint32_t bf0 = f2tf(pwg[(k0 + tig) * 64 + col]);
            uint32_t bf1 = f2tf(pwg[(k0 + tig + 4) * 64 + col]);
#pragma unroll
            for (int mt = 0; mt < MT; ++mt)
                mma_tf32(acc[mt], a[mt][0], a[mt][1], a[mt][2], a[mt][3], bf0, bf1);
        }
        int col0 = warp * 8 + tig * 2;
        float bb0 = pb[band * 64 + col0];
        float bb1 = pb[band * 64 + col0 + 1];
#pragma unroll
        for (int mt = 0; mt < MT; ++mt) {
            int r0 = mt * 16 + grp;
            float2 v0 = make_float2(acc[mt][0] + bb0, acc[mt][1] + bb1);
            float2 v1 = make_float2(acc[mt][2] + bb0, acc[mt][3] + bb1);
            *(float2*)&g_p[(((size_t)b * T_ + t0 + r0) * NB_ + band) * 64 + col0] = v0;
            *(float2*)&g_p[(((size_t)b * T_ + t0 + r0 + 8) * NB_ + band) * 64 + col0] = v1;
        }
    }
}

// ---------------------------------------------------------------------------
// Kernel 3 (tensor-core GEMM1): cat[32,448] @ mix_w1[448,128] -> gelu -> ms
// then fp32 FFMA 128->16. grid (B*T/32), block 256.
// ---------------------------------------------------------------------------
#define CP 452
#define MP 132

__global__ __launch_bounds__(256) void k_mix_tc(
    const float* __restrict__ mw1, const float* __restrict__ mb1,
    const float* __restrict__ mw2, const float* __restrict__ mb2,
    float* __restrict__ out)
{
    extern __shared__ float sm[];
    float* cs = sm;                 // 32*452
    float* ms = sm + 32 * CP;       // 32*132

    const int bt0 = blockIdx.x * 32;
    const int tid = threadIdx.x;
    const int warp = tid >> 5, lane = tid & 31;
    const int grp = lane >> 2, tig = lane & 3;

    const float* cb = g_p + (size_t)bt0 * 448;
    for (int i = tid; i < 32 * 448; i += 256) {
        int r = i / 448, c = i - r * 448;
        cs[r * CP + c] = __uint_as_float(f2tf(cb[i]));
    }
    __syncthreads();

    {
        float acc[2][2][4];
#pragma unroll
        for (int mt = 0; mt < 2; ++mt)
#pragma unroll
            for (int nt = 0; nt < 2; ++nt)
#pragma unroll
                for (int c = 0; c < 4; ++c) acc[mt][nt][c] = 0.0f;

        for (int k0 = 0; k0 < 448; k0 += 8) {
            uint32_t a[2][4];
#pragma unroll
            for (int mt = 0; mt < 2; ++mt) {
                int r0 = mt * 16 + grp;
                a[mt][0] = __float_as_uint(cs[r0 * CP + k0 + tig]);
                a[mt][1] = __float_as_uint(cs[(r0 + 8) * CP + k0 + tig]);
                a[mt][2] = __float_as_uint(cs[r0 * CP + k0 + tig + 4]);
                a[mt][3] = __float_as_uint(cs[(r0 + 8) * CP + k0 + tig + 4]);
            }
#pragma unroll
            for (int nt = 0; nt < 2; ++nt) {
                int col = warp * 16 + nt * 8 + grp;
                uint32_t bf0 = f2tf(mw1[(k0 + tig) * 128 + col]);
                uint32_t bf1 = f2tf(mw1[(k0 + tig + 4) * 128 + col]);
#pragma unroll
                for (int mt = 0; mt < 2; ++mt)
                    mma_tf32(acc[mt][nt], a[mt][0], a[mt][1], a[mt][2], a[mt][3], bf0, bf1);
            }
        }
#pragma unroll
        for (int nt = 0; nt < 2; ++nt) {
            int col0 = warp * 16 + nt * 8 + tig * 2;
            float bb0 = mb1[col0];
            float bb1 = mb1[col0 + 1];
#pragma unroll
            for (int mt = 0; mt < 2; ++mt) {
                int r0 = mt * 16 + grp;
                ms[r0 * MP + col0]           = gelu_exact(acc[mt][nt][0] + bb0);
                ms[r0 * MP + col0 + 1]       = gelu_exact(acc[mt][nt][1] + bb1);
                ms[(r0 + 8) * MP + col0]     = gelu_exact(acc[mt][nt][2] + bb0);
                ms[(r0 + 8) * MP + col0 + 1] = gelu_exact(acc[mt][nt][3] + bb1);
            }
        }
    }
    __syncthreads();

    {
        const int o = tid & 15, tb = tid >> 4;
        const float* wc = mw2 + o;
        const float bo = mb2[o];
#pragma unroll
        for (int h = 0; h < 2; ++h) {
            int tt = tb + h * 16;
            float acc = 0.0f;
            for (int e = 0; e < 128; e += 4) {
                float4 mv = *(const float4*)&ms[tt * MP + e];
                acc = fmaf(mv.x, wc[(e + 0) * 16], acc);
                acc = fmaf(mv.y, wc[(e + 1) * 16], acc);
                acc = fmaf(mv.z, wc[(e + 2) * 16], acc);
                acc = fmaf(mv.w, wc[(e + 3) * 16], acc);
            }
            out[(size_t)(bt0 + tt) * 16 + o] = acc + bo;
        }
    }
}

// ---------------------------------------------------------------------------
extern "C" void kernel_launch(void* const* d_in, const int* in_sizes, int n_in,
                              void* d_out, int out_size)
{
    const float* x      = (const float*)d_in[0];
    const float* conv_w = (const float*)d_in[1];
    const float* conv_b = (const float*)d_in[2];
    const float* dec_g  = (const float*)d_in[3];
    const float* dec_b  = (const float*)d_in[4];
    const float* n2_g   = (const float*)d_in[5];
    const float* n2_b   = (const float*)d_in[6];
    const float* ffn_w1 = (const float*)d_in[7];
    const float* ffn_b1 = (const float*)d_in[8];
    const float* ffn_w2 = (const float*)d_in[9];
    const float* ffn_b2 = (const float*)d_in[10];
    const float* proj_w = (const float*)d_in[11];
    const float* proj_b = (const float*)d_in[12];
    const float* mix_w1 = (const float*)d_in[13];
    const float* mix_b1 = (const float*)d_in[14];
    const float* mix_w2 = (const float*)d_in[15];
    const float* mix_b2 = (const float*)d_in[16];
    float* out = (float*)d_out;

    const int smem_ffn = 64 * (ZP * 2 + UP) * 4;            // 134144 B
    const int smem_mix = (32 * CP + 32 * MP) * 4;           // 74752 B
    cudaFuncSetAttribute(k_ffn_tc, cudaFuncAttributeMaxDynamicSharedMemorySize, smem_ffn);
    cudaFuncSetAttribute(k_mix_tc, cudaFuncAttributeMaxDynamicSharedMemorySize, smem_mix);

    dim3 g1(T_ / 32, B_, NB_);
    k_conv_tc<<<g1, 256>>>(x, conv_w, conv_b, dec_g, dec_b);

    dim3 g2(T_ / 64, B_, NB_);
    k_ffn_tc<<<g2, 256, smem_ffn>>>(n2_g, n2_b, ffn_w1, ffn_b1, ffn_w2, ffn_b2, proj_w, proj_b);

    dim3 g3((B_ * T_) / 32);
    k_mix_tc<<<g3, 256, smem_mix>>>(mix_w1, mix_b1, mix_w2, mix_b2, out);
}